// round 1
// baseline (speedup 1.0000x reference)
#include <cuda_runtime.h>
#include <cuda_bf16.h>
#include <mma.h>
using namespace nvcuda;

typedef __nv_bfloat16 bf16;

#define NTOK 4096
#define DIMD 384
#define INNER 1536
#define H2 3072
#define NE 5
#define KSZ 31
#define BT 4
#define TT 1024
#define SQ 48

// ---------------- device scratch (no allocs allowed) ----------------
__device__ float g_x[NTOK * DIMD];            // LN output
__device__ float g_h[NTOK * DIMD];            // conv output (tok) fp32
__device__ bf16  g_hbf[NTOK * DIMD];          // conv output bf16
__device__ float g_r1[NTOK * DIMD];           // router hidden pre-act (fp32)
__device__ bf16  g_we1[NE * DIMD * H2];
__device__ bf16  g_we2[NE * INNER * H2];
__device__ bf16  g_we3[NE * INNER * DIMD];
__device__ bf16  g_rw1[DIMD * DIMD];
__device__ int   g_cnt[NE];
__device__ int   g_list[NE * NTOK];
__device__ int   g_slot[NTOK * 2];
__device__ float g_wtok[NTOK * 2];
__device__ bf16  g_pre[(size_t)NE * NTOK * H2];     // 126 MB
__device__ bf16  g_act[(size_t)NE * NTOK * INNER];  // 63 MB
__device__ float g_eo[(size_t)NE * NTOK * DIMD];    // 31 MB
__device__ float g_y[NTOK * DIMD];
__device__ float g_gate[BT * DIMD];

__device__ __forceinline__ float siluf(float v) { return v / (1.f + __expf(-v)); }

// ---------------- small kernels ----------------
__global__ void k_convert(const float* __restrict__ s, int mode, int n) {
    int i = blockIdx.x * blockDim.x + threadIdx.x;
    if (i >= n) return;
    bf16* d = (mode == 0) ? g_we1 : (mode == 1) ? g_we2 : (mode == 2) ? g_we3 : g_rw1;
    d[i] = __float2bfloat16(s[i]);
}

__global__ void k_ln(const float* __restrict__ res, const float* __restrict__ g,
                     const float* __restrict__ b) {
    int n = blockIdx.x;
    int t = threadIdx.x;  // 128
    const float* r = res + (size_t)n * DIMD;
    float s = 0.f, s2 = 0.f;
    for (int i = t; i < DIMD; i += 128) { float v = r[i]; s += v; s2 += v * v; }
    for (int o = 16; o; o >>= 1) {
        s  += __shfl_down_sync(0xffffffffu, s, o);
        s2 += __shfl_down_sync(0xffffffffu, s2, o);
    }
    __shared__ float ss[4], ss2[4];
    int w = t >> 5;
    if ((t & 31) == 0) { ss[w] = s; ss2[w] = s2; }
    __syncthreads();
    if (t == 0) {
        float a = ss[0] + ss[1] + ss[2] + ss[3];
        float a2 = ss2[0] + ss2[1] + ss2[2] + ss2[3];
        float mu = a / DIMD;
        float var = a2 / DIMD - mu * mu;
        ss[0] = mu; ss2[0] = rsqrtf(var + 1e-5f);
    }
    __syncthreads();
    float mu = ss[0], rs = ss2[0];
    for (int i = t; i < DIMD; i += 128)
        g_x[(size_t)n * DIMD + i] = (r[i] - mu) * rs * g[i] + b[i];
}

__global__ void k_conv(const float* __restrict__ w, const float* __restrict__ cb) {
    int i = blockIdx.x * blockDim.x + threadIdx.x;
    if (i >= NTOK * DIMD) return;
    int d = i % DIMD;
    int nt = i / DIMD;
    int b = nt / TT, t = nt % TT;
    float acc = cb[d];
    const float* wd = w + d * KSZ;
#pragma unroll
    for (int k = 0; k < KSZ; k++) {
        int tt = t + k - KSZ / 2;
        if (tt >= 0 && tt < TT) acc += g_x[((size_t)(b * TT + tt)) * DIMD + d] * wd[k];
    }
    g_h[i] = acc;
    g_hbf[i] = __float2bfloat16(acc);
}

__global__ void k_zero() {
    if (threadIdx.x < NE) g_cnt[threadIdx.x] = 0;
}

// router second stage + top-2 + list build (1 warp per token)
__global__ void k_router(const float* __restrict__ rw2, const float* __restrict__ rb2) {
    int gw = (blockIdx.x * blockDim.x + threadIdx.x) >> 5;
    int lane = threadIdx.x & 31;
    if (gw >= NTOK) return;
    float p[NE];
#pragma unroll
    for (int e = 0; e < NE; e++) p[e] = 0.f;
    const float* row = g_r1 + (size_t)gw * DIMD;
    for (int k = lane; k < DIMD; k += 32) {
        float v = siluf(row[k]);
#pragma unroll
        for (int e = 0; e < NE; e++) p[e] += v * rw2[k * NE + e];
    }
#pragma unroll
    for (int e = 0; e < NE; e++)
        for (int o = 16; o; o >>= 1) p[e] += __shfl_down_sync(0xffffffffu, p[e], o);
    if (lane == 0) {
        float rv[NE];
#pragma unroll
        for (int e = 0; e < NE; e++) rv[e] = p[e] + rb2[e];
        int i1 = 0;
#pragma unroll
        for (int e = 1; e < NE; e++) if (rv[e] > rv[i1]) i1 = e;
        int i2 = (i1 == 0) ? 1 : 0;
#pragma unroll
        for (int e = 0; e < NE; e++) if (e != i1 && rv[e] > rv[i2]) i2 = e;
        float e2 = __expf(rv[i2] - rv[i1]);
        float inv = 1.f / (1.f + e2);
        float w1 = inv, w2 = e2 * inv;
        int p1 = atomicAdd(&g_cnt[i1], 1);
        g_list[i1 * NTOK + p1] = gw;
        g_slot[gw * 2] = i1 * NTOK + p1;
        g_wtok[gw * 2] = w1;
        int p2 = atomicAdd(&g_cnt[i2], 1);
        g_list[i2 * NTOK + p2] = gw;
        g_slot[gw * 2 + 1] = i2 * NTOK + p2;
        g_wtok[gw * 2 + 1] = w2;
    }
}

// grid: (INNER/256, NTOK, NE)
__global__ void k_swiglu() {
    int e = blockIdx.z;
    int row = blockIdx.y;
    if (row >= g_cnt[e]) return;
    int c = blockIdx.x * blockDim.x + threadIdx.x;
    size_t rowg = (size_t)e * NTOK + row;
    const bf16* pr = g_pre + rowg * H2;
    float a = __bfloat162float(pr[c]);
    float g = __bfloat162float(pr[INNER + c]);
    g_act[rowg * INNER + c] = __float2bfloat16(a * siluf(g));
}

__global__ void k_combine() {
    int i = blockIdx.x * blockDim.x + threadIdx.x;
    if (i >= NTOK * DIMD) return;
    int n = i / DIMD, d = i % DIMD;
    float v = g_h[i];
    v += g_wtok[n * 2]     * g_eo[(size_t)g_slot[n * 2] * DIMD + d];
    v += g_wtok[n * 2 + 1] * g_eo[(size_t)g_slot[n * 2 + 1] * DIMD + d];
    g_y[i] = v;
}

__global__ void k_gate(const float* __restrict__ sw1, const float* __restrict__ sb1,
                       const float* __restrict__ sw2, const float* __restrict__ sb2,
                       const float* __restrict__ sres) {
    int b = blockIdx.x;
    int d = threadIdx.x;  // 384
    __shared__ float pooled[DIMD];
    __shared__ float s1[SQ];
    float acc = 0.f;
    float sr = sres[d];
#pragma unroll 4
    for (int t = 0; t < TT; t++) {
        size_t i = (size_t)(b * TT + t) * DIMD + d;
        acc += g_x[i] * sr + g_y[i];
    }
    pooled[d] = acc / TT;
    __syncthreads();
    if (d < SQ) {
        float a = sb1[d];
        for (int k = 0; k < DIMD; k++) a += pooled[k] * sw1[k * SQ + d];
        s1[d] = siluf(a);
    }
    __syncthreads();
    float ga = sb2[d];
#pragma unroll
    for (int q = 0; q < SQ; q++) ga += s1[q] * sw2[q * DIMD + d];
    g_gate[b * DIMD + d] = 1.f / (1.f + __expf(-ga));
}

__global__ void k_final(const float* __restrict__ res, float* __restrict__ out) {
    int i = blockIdx.x * blockDim.x + threadIdx.x;
    if (i >= NTOK * DIMD) return;
    int b = i / (TT * DIMD);
    int d = i % DIMD;
    out[i] = res[i] + g_y[i] * g_gate[b * DIMD + d];
}

// ---------------- GEMM: C[M,N] = A[M,K] @ B[K,N] + bias, bf16 in, fp32 acc ----
// MODE 0: router1   A=g_hbf         B=g_rw1  C=g_r1(f32)  K=384  N=384   M=4096
// MODE 1: expert1   A=g_hbf(gather) B=g_we1  C=g_pre(bf)  K=384  N=3072  M=cnt[e]
// MODE 2: expert2   A=g_act         B=g_we2  C=g_pre(bf)  K=1536 N=3072  M=cnt[e]
// MODE 3: expert3   A=g_act         B=g_we3  C=g_eo(f32)  K=1536 N=384   M=cnt[e]
template <int MODE>
__global__ void __launch_bounds__(256) k_gemm(const float* __restrict__ bias) {
    constexpr int K  = (MODE <= 1) ? DIMD : INNER;
    constexpr int NC = (MODE == 0 || MODE == 3) ? DIMD : H2;
    constexpr bool GATHER = (MODE == 1);
    constexpr bool USECNT = (MODE != 0);
    constexpr bool OUTBF  = (MODE == 1 || MODE == 2);

    int e = blockIdx.z;
    int M = USECNT ? g_cnt[e] : NTOK;
    int m0 = blockIdx.y << 7;
    if (m0 >= M) return;
    int n0 = blockIdx.x << 7;

    __shared__ __align__(16) unsigned char smem[49152];
    bf16* As = (bf16*)smem;                 // [128][32]
    bf16* Bs = (bf16*)(smem + 8192);        // [32][128]
    float* Cs = (float*)(smem + 16384);     // [64][128]

    int tid = threadIdx.x;

    // A source pointer
    const bf16* Abase;
    if (MODE == 0 || MODE == 1) Abase = g_hbf;
    else Abase = g_act + (size_t)e * NTOK * INNER;

    int arow = tid >> 1;
    int acol = (tid & 1) << 4;
    int gr = m0 + arow;
    int srcRow = GATHER ? g_list[e * NTOK + gr] : gr;
    const bf16* aptr = Abase + (size_t)srcRow * K + acol;

    // B source pointer
    const bf16* Bbase;
    if (MODE == 0) Bbase = g_rw1;
    else if (MODE == 1) Bbase = g_we1 + (size_t)e * DIMD * H2;
    else if (MODE == 2) Bbase = g_we2 + (size_t)e * INNER * H2;
    else Bbase = g_we3 + (size_t)e * INNER * DIMD;

    int brow = tid >> 3;
    int bcol = (tid & 7) << 4;
    const bf16* bptr = Bbase + (size_t)brow * NC + n0 + bcol;

    int warpId = tid >> 5, wm = warpId >> 1, wn = warpId & 1;

    wmma::fragment<wmma::accumulator, 16, 16, 16, float> acc[2][4];
#pragma unroll
    for (int i = 0; i < 2; i++)
#pragma unroll
        for (int j = 0; j < 4; j++) wmma::fill_fragment(acc[i][j], 0.f);

    for (int k0 = 0; k0 < K; k0 += 32) {
        uint4 a0 = *(const uint4*)(aptr + k0);
        uint4 a1 = *(const uint4*)(aptr + k0 + 8);
        *(uint4*)(As + arow * 32 + acol) = a0;
        *(uint4*)(As + arow * 32 + acol + 8) = a1;
        const bf16* bp = bptr + (size_t)k0 * NC;
        uint4 b0 = *(const uint4*)(bp);
        uint4 b1 = *(const uint4*)(bp + 8);
        *(uint4*)(Bs + brow * 128 + bcol) = b0;
        *(uint4*)(Bs + brow * 128 + bcol + 8) = b1;
        __syncthreads();
#pragma unroll
        for (int kk = 0; kk < 32; kk += 16) {
            wmma::fragment<wmma::matrix_a, 16, 16, 16, bf16, wmma::row_major> af[2];
            wmma::fragment<wmma::matrix_b, 16, 16, 16, bf16, wmma::row_major> bfm[4];
#pragma unroll
            for (int i = 0; i < 2; i++)
                wmma::load_matrix_sync(af[i], As + (wm * 32 + i * 16) * 32 + kk, 32);
#pragma unroll
            for (int j = 0; j < 4; j++)
                wmma::load_matrix_sync(bfm[j], Bs + kk * 128 + wn * 64 + j * 16, 128);
#pragma unroll
            for (int i = 0; i < 2; i++)
#pragma unroll
                for (int j = 0; j < 4; j++)
                    wmma::mma_sync(acc[i][j], af[i], bfm[j], acc[i][j]);
        }
        __syncthreads();
    }

    // epilogue in two 64-row halves through shared staging
    constexpr int biasStride = (MODE == 0) ? 0 : ((MODE == 3) ? DIMD : H2);
    size_t cBase;
    if (MODE == 0) cBase = 0;
    else if (MODE == 3) cBase = (size_t)e * NTOK * DIMD;
    else cBase = (size_t)e * NTOK * H2;

#pragma unroll
    for (int half = 0; half < 2; half++) {
        if ((wm >> 1) == half) {
#pragma unroll
            for (int i = 0; i < 2; i++)
#pragma unroll
                for (int j = 0; j < 4; j++)
                    wmma::store_matrix_sync(
                        Cs + ((wm & 1) * 32 + i * 16) * 128 + wn * 64 + j * 16,
                        acc[i][j], 128, wmma::mem_row_major);
        }
        __syncthreads();
#pragma unroll
        for (int it = 0; it < 32; it++) {
            int lin = tid + it * 256;
            int r = lin >> 7, c = lin & 127;
            int grow = m0 + half * 64 + r;
            if (grow < M) {
                float v = Cs[lin] + bias[(size_t)e * biasStride + n0 + c];
                size_t idx = cBase + (size_t)grow * NC + n0 + c;
                if (OUTBF) g_pre[idx] = __float2bfloat16(v);
                else if (MODE == 0) g_r1[idx] = v;
                else g_eo[idx] = v;
            }
        }
        __syncthreads();
    }
}

// ---------------- launch ----------------
extern "C" void kernel_launch(void* const* d_in, const int* in_sizes, int n_in,
                              void* d_out, int out_size) {
    const float* res    = (const float*)d_in[0];
    const float* ln_g   = (const float*)d_in[1];
    const float* ln_b   = (const float*)d_in[2];
    const float* conv_w = (const float*)d_in[3];
    const float* conv_b = (const float*)d_in[4];
    const float* rw1    = (const float*)d_in[5];
    const float* rb1    = (const float*)d_in[6];
    const float* rw2    = (const float*)d_in[7];
    const float* rb2    = (const float*)d_in[8];
    const float* we1    = (const float*)d_in[9];
    const float* be1    = (const float*)d_in[10];
    const float* we2    = (const float*)d_in[11];
    const float* be2    = (const float*)d_in[12];
    const float* we3    = (const float*)d_in[13];
    const float* be3    = (const float*)d_in[14];
    const float* sw1    = (const float*)d_in[15];
    const float* sb1    = (const float*)d_in[16];
    const float* sw2    = (const float*)d_in[17];
    const float* sb2    = (const float*)d_in[18];
    const float* sres   = (const float*)d_in[19];
    float* out = (float*)d_out;

    // weight conversions (fp32 -> bf16)
    k_convert<<<(NE * DIMD * H2 + 255) / 256, 256>>>(we1, 0, NE * DIMD * H2);
    k_convert<<<(NE * INNER * H2 + 255) / 256, 256>>>(we2, 1, NE * INNER * H2);
    k_convert<<<(NE * INNER * DIMD + 255) / 256, 256>>>(we3, 2, NE * INNER * DIMD);
    k_convert<<<(DIMD * DIMD + 255) / 256, 256>>>(rw1, 3, DIMD * DIMD);

    k_ln<<<NTOK, 128>>>(res, ln_g, ln_b);
    k_conv<<<(NTOK * DIMD + 255) / 256, 256>>>(conv_w, conv_b);
    k_zero<<<1, 32>>>();

    k_gemm<0><<<dim3(DIMD / 128, NTOK / 128, 1), 256>>>(rb1);     // router hidden
    k_router<<<NTOK / 4, 128>>>(rw2, rb2);                        // top-2 + lists

    k_gemm<1><<<dim3(H2 / 128, NTOK / 128, NE), 256>>>(be1);      // expert fc1
    k_swiglu<<<dim3(INNER / 256, NTOK, NE), 256>>>();
    k_gemm<2><<<dim3(H2 / 128, NTOK / 128, NE), 256>>>(be2);      // expert fc2
    k_swiglu<<<dim3(INNER / 256, NTOK, NE), 256>>>();
    k_gemm<3><<<dim3(DIMD / 128, NTOK / 128, NE), 256>>>(be3);    // expert fc3

    k_combine<<<(NTOK * DIMD + 255) / 256, 256>>>();
    k_gate<<<BT, DIMD>>>(sw1, sb1, sw2, sb2, sres);
    k_final<<<(NTOK * DIMD + 255) / 256, 256>>>(res, out);
}

// round 3
// speedup vs baseline: 1.9605x; 1.9605x over previous
#include <cstdint>
#include <cuda_runtime.h>
#include <cuda_bf16.h>
#include <mma.h>
using namespace nvcuda;

typedef __nv_bfloat16 bf16;

#define NTOK 4096
#define DIMD 384
#define INNER 1536
#define H2 3072
#define NE 5
#define KSZ 31
#define BT 4
#define TT 1024
#define SQ 48

// ---------------- device scratch (no allocs allowed) ----------------
__device__ float g_x[NTOK * DIMD];            // LN output
__device__ float g_h[NTOK * DIMD];            // conv output (tok) fp32
__device__ bf16  g_hbf[NTOK * DIMD];          // conv output bf16
__device__ float g_r1[NTOK * DIMD];           // router hidden pre-act (fp32)
__device__ bf16  g_we1[NE * DIMD * H2];
__device__ bf16  g_we2[NE * INNER * H2];
__device__ bf16  g_we3[NE * INNER * DIMD];
__device__ bf16  g_rw1[DIMD * DIMD];
__device__ int   g_cnt[NE];
__device__ int   g_list[NE * NTOK];
__device__ int   g_slot[NTOK * 2];
__device__ float g_wtok[NTOK * 2];
__device__ bf16  g_pre[(size_t)NE * NTOK * H2];     // 126 MB
__device__ bf16  g_act[(size_t)NE * NTOK * INNER];  // 63 MB
__device__ float g_eo[(size_t)NE * NTOK * DIMD];    // 31 MB
__device__ float g_y[NTOK * DIMD];
__device__ float g_gate[BT * DIMD];

__device__ __forceinline__ float siluf(float v) { return v / (1.f + __expf(-v)); }

__device__ __forceinline__ void cpa16(void* dst, const void* src) {
    unsigned int d = (unsigned int)__cvta_generic_to_shared(dst);
    asm volatile("cp.async.cg.shared.global [%0], [%1], 16;\n" :: "r"(d), "l"(src));
}
#define CP_COMMIT asm volatile("cp.async.commit_group;\n")
#define CP_WAIT1  asm volatile("cp.async.wait_group 1;\n")
#define CP_WAIT0  asm volatile("cp.async.wait_group 0;\n")

// ---------------- small kernels ----------------
__global__ void k_convert(const float* __restrict__ s, int mode, int n) {
    int i = blockIdx.x * blockDim.x + threadIdx.x;
    if (i >= n) return;
    bf16* d = (mode == 0) ? g_we1 : (mode == 1) ? g_we2 : (mode == 2) ? g_we3 : g_rw1;
    d[i] = __float2bfloat16(s[i]);
}

__global__ void k_ln(const float* __restrict__ res, const float* __restrict__ g,
                     const float* __restrict__ b) {
    int n = blockIdx.x;
    int t = threadIdx.x;  // 128
    const float* r = res + (size_t)n * DIMD;
    float s = 0.f, s2 = 0.f;
    for (int i = t; i < DIMD; i += 128) { float v = r[i]; s += v; s2 += v * v; }
    for (int o = 16; o; o >>= 1) {
        s  += __shfl_down_sync(0xffffffffu, s, o);
        s2 += __shfl_down_sync(0xffffffffu, s2, o);
    }
    __shared__ float ss[4], ss2[4];
    int w = t >> 5;
    if ((t & 31) == 0) { ss[w] = s; ss2[w] = s2; }
    __syncthreads();
    if (t == 0) {
        float a = ss[0] + ss[1] + ss[2] + ss[3];
        float a2 = ss2[0] + ss2[1] + ss2[2] + ss2[3];
        float mu = a / DIMD;
        float var = a2 / DIMD - mu * mu;
        ss[0] = mu; ss2[0] = rsqrtf(var + 1e-5f);
    }
    __syncthreads();
    float mu = ss[0], rs = ss2[0];
    for (int i = t; i < DIMD; i += 128)
        g_x[(size_t)n * DIMD + i] = (r[i] - mu) * rs * g[i] + b[i];
}

__global__ void k_conv(const float* __restrict__ w, const float* __restrict__ cb) {
    int i = blockIdx.x * blockDim.x + threadIdx.x;
    if (i >= NTOK * DIMD) return;
    int d = i % DIMD;
    int nt = i / DIMD;
    int b = nt / TT, t = nt % TT;
    float acc = cb[d];
    const float* wd = w + d * KSZ;
#pragma unroll
    for (int k = 0; k < KSZ; k++) {
        int tt = t + k - KSZ / 2;
        if (tt >= 0 && tt < TT) acc += g_x[((size_t)(b * TT + tt)) * DIMD + d] * wd[k];
    }
    g_h[i] = acc;
    g_hbf[i] = __float2bfloat16(acc);
}

__global__ void k_zero() {
    if (threadIdx.x < NE) g_cnt[threadIdx.x] = 0;
}

// router second stage + top-2 + list build (1 warp per token)
__global__ void k_router(const float* __restrict__ rw2, const float* __restrict__ rb2) {
    int gw = (blockIdx.x * blockDim.x + threadIdx.x) >> 5;
    int lane = threadIdx.x & 31;
    if (gw >= NTOK) return;
    float p[NE];
#pragma unroll
    for (int e = 0; e < NE; e++) p[e] = 0.f;
    const float* row = g_r1 + (size_t)gw * DIMD;
    for (int k = lane; k < DIMD; k += 32) {
        float v = siluf(row[k]);
#pragma unroll
        for (int e = 0; e < NE; e++) p[e] += v * rw2[k * NE + e];
    }
#pragma unroll
    for (int e = 0; e < NE; e++)
        for (int o = 16; o; o >>= 1) p[e] += __shfl_down_sync(0xffffffffu, p[e], o);
    if (lane == 0) {
        float rv[NE];
#pragma unroll
        for (int e = 0; e < NE; e++) rv[e] = p[e] + rb2[e];
        int i1 = 0;
#pragma unroll
        for (int e = 1; e < NE; e++) if (rv[e] > rv[i1]) i1 = e;
        int i2 = (i1 == 0) ? 1 : 0;
#pragma unroll
        for (int e = 0; e < NE; e++) if (e != i1 && rv[e] > rv[i2]) i2 = e;
        float e2 = __expf(rv[i2] - rv[i1]);
        float inv = 1.f / (1.f + e2);
        float w1 = inv, w2 = e2 * inv;
        int p1 = atomicAdd(&g_cnt[i1], 1);
        g_list[i1 * NTOK + p1] = gw;
        g_slot[gw * 2] = i1 * NTOK + p1;
        g_wtok[gw * 2] = w1;
        int p2 = atomicAdd(&g_cnt[i2], 1);
        g_list[i2 * NTOK + p2] = gw;
        g_slot[gw * 2 + 1] = i2 * NTOK + p2;
        g_wtok[gw * 2 + 1] = w2;
    }
}

// grid: (INNER/256, NTOK, NE)
__global__ void k_swiglu() {
    int e = blockIdx.z;
    int row = blockIdx.y;
    if (row >= g_cnt[e]) return;
    int c = blockIdx.x * blockDim.x + threadIdx.x;
    size_t rowg = (size_t)e * NTOK + row;
    const bf16* pr = g_pre + rowg * H2;
    float a = __bfloat162float(pr[c]);
    float g = __bfloat162float(pr[INNER + c]);
    g_act[rowg * INNER + c] = __float2bfloat16(a * siluf(g));
}

__global__ void k_combine() {
    int i = blockIdx.x * blockDim.x + threadIdx.x;
    if (i >= NTOK * DIMD) return;
    int n = i / DIMD, d = i % DIMD;
    float v = g_h[i];
    v += g_wtok[n * 2]     * g_eo[(size_t)g_slot[n * 2] * DIMD + d];
    v += g_wtok[n * 2 + 1] * g_eo[(size_t)g_slot[n * 2 + 1] * DIMD + d];
    g_y[i] = v;
}

__global__ void k_gate(const float* __restrict__ sw1, const float* __restrict__ sb1,
                       const float* __restrict__ sw2, const float* __restrict__ sb2,
                       const float* __restrict__ sres) {
    int b = blockIdx.x;
    int d = threadIdx.x;  // 384
    __shared__ float pooled[DIMD];
    __shared__ float s1[SQ];
    float acc = 0.f;
    float sr = sres[d];
#pragma unroll 4
    for (int t = 0; t < TT; t++) {
        size_t i = (size_t)(b * TT + t) * DIMD + d;
        acc += g_x[i] * sr + g_y[i];
    }
    pooled[d] = acc / TT;
    __syncthreads();
    if (d < SQ) {
        float a = sb1[d];
        for (int k = 0; k < DIMD; k++) a += pooled[k] * sw1[k * SQ + d];
        s1[d] = siluf(a);
    }
    __syncthreads();
    float ga = sb2[d];
#pragma unroll
    for (int q = 0; q < SQ; q++) ga += s1[q] * sw2[q * DIMD + d];
    g_gate[b * DIMD + d] = 1.f / (1.f + __expf(-ga));
}

__global__ void k_final(const float* __restrict__ res, float* __restrict__ out) {
    int i = blockIdx.x * blockDim.x + threadIdx.x;
    if (i >= NTOK * DIMD) return;
    int b = i / (TT * DIMD);
    int d = i % DIMD;
    out[i] = res[i] + g_y[i] * g_gate[b * DIMD + d];
}

// ---------------- GEMM: C[M,N] = A[M,K] @ B[K,N] + bias, bf16 in, fp32 acc ----
// Padded smem strides (conflict-free) + cp.async 2-stage pipeline.
// MODE 0: router1   A=g_hbf         B=g_rw1  C=g_r1(f32)  K=384  N=384   M=4096
// MODE 1: expert1   A=g_hbf(gather) B=g_we1  C=g_pre(bf)  K=384  N=3072  M=cnt[e]
// MODE 2: expert2   A=g_act         B=g_we2  C=g_pre(bf)  K=1536 N=3072  M=cnt[e]
// MODE 3: expert3   A=g_act         B=g_we3  C=g_eo(f32)  K=1536 N=384   M=cnt[e]
#define ALD 40   // As ldm (bf16), 80B row stride
#define BLD 136  // Bs ldm (bf16), 272B row stride
#define CLD 132  // Cs ldm (f32),  528B row stride

template <int MODE>
__global__ void __launch_bounds__(256) k_gemm(const float* __restrict__ bias) {
    constexpr int K  = (MODE <= 1) ? DIMD : INNER;
    constexpr int NC = (MODE == 0 || MODE == 3) ? DIMD : H2;
    constexpr bool GATHER = (MODE == 1);
    constexpr bool USECNT = (MODE != 0);
    constexpr bool OUTBF  = (MODE == 1 || MODE == 2);
    constexpr int KT = K / 32;

    int e = blockIdx.z;
    int M = USECNT ? g_cnt[e] : NTOK;
    int m0 = blockIdx.y << 7;
    if (m0 >= M) return;
    int n0 = blockIdx.x << 7;

    // smem: 2 x As(128x40 bf16 = 10240B) + 2 x Bs(32x136 bf16 = 8704B) = 37888B
    // epilogue Cs (64x132 f32 = 33792B) reuses the same space after mainloop.
    __shared__ __align__(16) unsigned char smem[2 * 128 * ALD * 2 + 2 * 32 * BLD * 2];
    bf16* As0 = (bf16*)smem;
    bf16* As1 = As0 + 128 * ALD;
    bf16* Bs0 = (bf16*)(smem + 2 * 128 * ALD * 2);
    bf16* Bs1 = Bs0 + 32 * BLD;
    float* Cs = (float*)smem;

    int tid = threadIdx.x;

    // A source
    const bf16* Abase;
    if (MODE == 0 || MODE == 1) Abase = g_hbf;
    else Abase = g_act + (size_t)e * NTOK * INNER;

    // A load mapping: 512 16B-chunks; chunk c: row=c>>2, col=(c&3)*8. thread does c=tid, tid+256.
    int ar0 = tid >> 2;           // rows 0..63
    int acol = (tid & 3) << 3;    // 0,8,16,24
    int gr0 = m0 + ar0, gr1 = m0 + ar0 + 64;
    int sr0 = GATHER ? g_list[e * NTOK + gr0] : gr0;
    int sr1 = GATHER ? g_list[e * NTOK + gr1] : gr1;
    const bf16* aptr0 = Abase + (size_t)sr0 * K + acol;
    const bf16* aptr1 = Abase + (size_t)sr1 * K + acol;

    // B source
    const bf16* Bbase;
    if (MODE == 0) Bbase = g_rw1;
    else if (MODE == 1) Bbase = g_we1 + (size_t)e * DIMD * H2;
    else if (MODE == 2) Bbase = g_we2 + (size_t)e * INNER * H2;
    else Bbase = g_we3 + (size_t)e * INNER * DIMD;

    // B load mapping: 512 chunks; chunk c: row=c>>4, col=(c&15)*8. thread does c=tid, tid+256.
    int br0 = tid >> 4;           // 0..15
    int bcol = (tid & 15) << 3;   // 0..120
    const bf16* bptr0 = Bbase + (size_t)br0 * NC + n0 + bcol;
    const bf16* bptr1 = Bbase + (size_t)(br0 + 16) * NC + n0 + bcol;

    int warpId = tid >> 5, wm = warpId >> 1, wn = warpId & 1;

    wmma::fragment<wmma::accumulator, 16, 16, 16, float> acc[2][4];
#pragma unroll
    for (int i = 0; i < 2; i++)
#pragma unroll
        for (int j = 0; j < 4; j++) wmma::fill_fragment(acc[i][j], 0.f);

    // prologue: load K-step 0 into buffer 0
    {
        cpa16(As0 + ar0 * ALD + acol, aptr0);
        cpa16(As0 + (ar0 + 64) * ALD + acol, aptr1);
        cpa16(Bs0 + br0 * BLD + bcol, bptr0);
        cpa16(Bs0 + (br0 + 16) * BLD + bcol, bptr1);
        CP_COMMIT;
    }

    for (int kt = 0; kt < KT; kt++) {
        int nb = kt & 1;
        if (kt + 1 < KT) {
            int k0 = (kt + 1) * 32;
            bf16* Ad = (nb == 0) ? As1 : As0;
            bf16* Bd = (nb == 0) ? Bs1 : Bs0;
            cpa16(Ad + ar0 * ALD + acol, aptr0 + k0);
            cpa16(Ad + (ar0 + 64) * ALD + acol, aptr1 + k0);
            cpa16(Bd + br0 * BLD + bcol, bptr0 + (size_t)k0 * NC);
            cpa16(Bd + (br0 + 16) * BLD + bcol, bptr1 + (size_t)k0 * NC);
            CP_COMMIT;
            CP_WAIT1;
        } else {
            CP_WAIT0;
        }
        __syncthreads();
        const bf16* Ab = (nb == 0) ? As0 : As1;
        const bf16* Bb = (nb == 0) ? Bs0 : Bs1;
#pragma unroll
        for (int kk = 0; kk < 32; kk += 16) {
            wmma::fragment<wmma::matrix_a, 16, 16, 16, bf16, wmma::row_major> af[2];
            wmma::fragment<wmma::matrix_b, 16, 16, 16, bf16, wmma::row_major> bfm[4];
#pragma unroll
            for (int i = 0; i < 2; i++)
                wmma::load_matrix_sync(af[i], Ab + (wm * 32 + i * 16) * ALD + kk, ALD);
#pragma unroll
            for (int j = 0; j < 4; j++)
                wmma::load_matrix_sync(bfm[j], Bb + kk * BLD + wn * 64 + j * 16, BLD);
#pragma unroll
            for (int i = 0; i < 2; i++)
#pragma unroll
                for (int j = 0; j < 4; j++)
                    wmma::mma_sync(acc[i][j], af[i], bfm[j], acc[i][j]);
        }
        __syncthreads();
    }

    // epilogue in two 64-row halves via shared staging (reuses load buffers)
    constexpr int biasStride = (MODE == 0) ? 0 : ((MODE == 3) ? DIMD : H2);
    size_t cBase;
    if (MODE == 0) cBase = 0;
    else if (MODE == 3) cBase = (size_t)e * NTOK * DIMD;
    else cBase = (size_t)e * NTOK * H2;

#pragma unroll
    for (int half = 0; half < 2; half++) {
        if ((wm >> 1) == half) {
#pragma unroll
            for (int i = 0; i < 2; i++)
#pragma unroll
                for (int j = 0; j < 4; j++)
                    wmma::store_matrix_sync(
                        Cs + ((wm & 1) * 32 + i * 16) * CLD + wn * 64 + j * 16,
                        acc[i][j], CLD, wmma::mem_row_major);
        }
        __syncthreads();
#pragma unroll
        for (int it = 0; it < 32; it++) {
            int lin = tid + it * 256;
            int r = lin >> 7, c = lin & 127;
            int grow = m0 + half * 64 + r;
            if (grow < M) {
                float v = Cs[r * CLD + c] + bias[(size_t)e * biasStride + n0 + c];
                size_t idx = cBase + (size_t)grow * NC + n0 + c;
                if (OUTBF) g_pre[idx] = __float2bfloat16(v);
                else if (MODE == 0) g_r1[idx] = v;
                else g_eo[idx] = v;
            }
        }
        __syncthreads();
    }
}

// ---------------- launch ----------------
extern "C" void kernel_launch(void* const* d_in, const int* in_sizes, int n_in,
                              void* d_out, int out_size) {
    const float* res    = (const float*)d_in[0];
    const float* ln_g   = (const float*)d_in[1];
    const float* ln_b   = (const float*)d_in[2];
    const float* conv_w = (const float*)d_in[3];
    const float* conv_b = (const float*)d_in[4];
    const float* rw1    = (const float*)d_in[5];
    const float* rb1    = (const float*)d_in[6];
    const float* rw2    = (const float*)d_in[7];
    const float* rb2    = (const float*)d_in[8];
    const float* we1    = (const float*)d_in[9];
    const float* be1    = (const float*)d_in[10];
    const float* we2    = (const float*)d_in[11];
    const float* be2    = (const float*)d_in[12];
    const float* we3    = (const float*)d_in[13];
    const float* be3    = (const float*)d_in[14];
    const float* sw1    = (const float*)d_in[15];
    const float* sb1    = (const float*)d_in[16];
    const float* sw2    = (const float*)d_in[17];
    const float* sb2    = (const float*)d_in[18];
    const float* sres   = (const float*)d_in[19];
    float* out = (float*)d_out;

    // weight conversions (fp32 -> bf16)
    k_convert<<<(NE * DIMD * H2 + 255) / 256, 256>>>(we1, 0, NE * DIMD * H2);
    k_convert<<<(NE * INNER * H2 + 255) / 256, 256>>>(we2, 1, NE * INNER * H2);
    k_convert<<<(NE * INNER * DIMD + 255) / 256, 256>>>(we3, 2, NE * INNER * DIMD);
    k_convert<<<(DIMD * DIMD + 255) / 256, 256>>>(rw1, 3, DIMD * DIMD);

    k_ln<<<NTOK, 128>>>(res, ln_g, ln_b);
    k_conv<<<(NTOK * DIMD + 255) / 256, 256>>>(conv_w, conv_b);
    k_zero<<<1, 32>>>();

    k_gemm<0><<<dim3(DIMD / 128, NTOK / 128, 1), 256>>>(rb1);     // router hidden
    k_router<<<NTOK / 4, 128>>>(rw2, rb2);                        // top-2 + lists

    k_gemm<1><<<dim3(H2 / 128, NTOK / 128, NE), 256>>>(be1);      // expert fc1
    k_swiglu<<<dim3(INNER / 256, NTOK, NE), 256>>>();
    k_gemm<2><<<dim3(H2 / 128, NTOK / 128, NE), 256>>>(be2);      // expert fc2
    k_swiglu<<<dim3(INNER / 256, NTOK, NE), 256>>>();
    k_gemm<3><<<dim3(DIMD / 128, NTOK / 128, NE), 256>>>(be3);    // expert fc3

    k_combine<<<(NTOK * DIMD + 255) / 256, 256>>>();
    k_gate<<<BT, DIMD>>>(sw1, sb1, sw2, sb2, sres);
    k_final<<<(NTOK * DIMD + 255) / 256, 256>>>(res, out);
}

// round 4
// speedup vs baseline: 2.4877x; 1.2689x over previous
#include <cstdint>
#include <cuda_runtime.h>
#include <cuda_bf16.h>
#include <mma.h>
using namespace nvcuda;

typedef __nv_bfloat16 bf16;

#define NTOK 4096
#define DIMD 384
#define INNER 1536
#define H2 3072
#define NE 5
#define KSZ 31
#define BT 4
#define TT 1024
#define SQ 48

// ---------------- device scratch (no allocs allowed) ----------------
__device__ float g_x[NTOK * DIMD];            // LN output
__device__ float g_h[NTOK * DIMD];            // conv output (tok) fp32
__device__ bf16  g_hbf[NTOK * DIMD];          // conv output bf16
__device__ float g_r1[NTOK * DIMD];           // router hidden pre-act (fp32)
__device__ bf16  g_we1[NE * DIMD * H2];       // PERMUTED pairs (2j=a_j, 2j+1=g_j)
__device__ bf16  g_we2[NE * INNER * H2];      // PERMUTED pairs
__device__ bf16  g_we3[NE * INNER * DIMD];
__device__ bf16  g_rw1[DIMD * DIMD];
__device__ int   g_cnt[NE];
__device__ int   g_list[NE * NTOK];
__device__ int   g_slot[NTOK * 2];
__device__ float g_wtok[NTOK * 2];
__device__ bf16  g_act1[(size_t)NE * NTOK * INNER];  // fc1 fused output
__device__ bf16  g_act2[(size_t)NE * NTOK * INNER];  // fc2 fused output
__device__ float g_eo[(size_t)NE * NTOK * DIMD];     // fc3 output
__device__ float g_y[NTOK * DIMD];
__device__ float g_pool_part[BT * 16 * DIMD];
__device__ float g_gate[BT * DIMD];

__device__ __forceinline__ float siluf(float v) { return v / (1.f + __expf(-v)); }

__device__ __forceinline__ void cpa16(void* dst, const void* src) {
    unsigned int d = (unsigned int)__cvta_generic_to_shared(dst);
    asm volatile("cp.async.cg.shared.global [%0], [%1], 16;\n" :: "r"(d), "l"(src));
}
#define CP_COMMIT asm volatile("cp.async.commit_group;\n")
#define CP_WAIT1  asm volatile("cp.async.wait_group 1;\n")
#define CP_WAIT0  asm volatile("cp.async.wait_group 0;\n")

// ---------------- small kernels ----------------
// mode 0: we1 (permuted), 1: we2 (permuted), 2: we3, 3: rw1
__global__ void k_convert(const float* __restrict__ s, int mode, int n) {
    int i = blockIdx.x * blockDim.x + threadIdx.x;
    if (i >= n) return;
    float v = s[i];
    if (mode == 0 || mode == 1) {
        int c = i % H2;
        int rowg = i / H2;  // e*rows + r
        int cp = (c < INNER) ? (2 * c) : (2 * (c - INNER) + 1);
        bf16* d = (mode == 0) ? g_we1 : g_we2;
        d[(size_t)rowg * H2 + cp] = __float2bfloat16(v);
    } else {
        bf16* d = (mode == 2) ? g_we3 : g_rw1;
        d[i] = __float2bfloat16(v);
    }
}

__global__ void k_ln(const float* __restrict__ res, const float* __restrict__ g,
                     const float* __restrict__ b) {
    int n = blockIdx.x;
    int t = threadIdx.x;  // 128
    const float* r = res + (size_t)n * DIMD;
    float s = 0.f, s2 = 0.f;
    for (int i = t; i < DIMD; i += 128) { float v = r[i]; s += v; s2 += v * v; }
    for (int o = 16; o; o >>= 1) {
        s  += __shfl_down_sync(0xffffffffu, s, o);
        s2 += __shfl_down_sync(0xffffffffu, s2, o);
    }
    __shared__ float ss[4], ss2[4];
    int w = t >> 5;
    if ((t & 31) == 0) { ss[w] = s; ss2[w] = s2; }
    __syncthreads();
    if (t == 0) {
        float a = ss[0] + ss[1] + ss[2] + ss[3];
        float a2 = ss2[0] + ss2[1] + ss2[2] + ss2[3];
        float mu = a / DIMD;
        float var = a2 / DIMD - mu * mu;
        ss[0] = mu; ss2[0] = rsqrtf(var + 1e-5f);
    }
    __syncthreads();
    float mu = ss[0], rs = ss2[0];
    for (int i = t; i < DIMD; i += 128)
        g_x[(size_t)n * DIMD + i] = (r[i] - mu) * rs * g[i] + b[i];
}

__global__ void k_conv(const float* __restrict__ w, const float* __restrict__ cb) {
    int i = blockIdx.x * blockDim.x + threadIdx.x;
    if (i >= NTOK * DIMD) return;
    int d = i % DIMD;
    int nt = i / DIMD;
    int b = nt / TT, t = nt % TT;
    float acc = cb[d];
    const float* wd = w + d * KSZ;
#pragma unroll
    for (int k = 0; k < KSZ; k++) {
        int tt = t + k - KSZ / 2;
        if (tt >= 0 && tt < TT) acc += g_x[((size_t)(b * TT + tt)) * DIMD + d] * wd[k];
    }
    g_h[i] = acc;
    g_hbf[i] = __float2bfloat16(acc);
}

__global__ void k_zero() {
    int i = threadIdx.x;
    if (i < NE) g_cnt[i] = 0;
}

// router second stage + top-2 + list build (1 warp per token)
__global__ void k_router(const float* __restrict__ rw2, const float* __restrict__ rb2) {
    int gw = (blockIdx.x * blockDim.x + threadIdx.x) >> 5;
    int lane = threadIdx.x & 31;
    if (gw >= NTOK) return;
    float p[NE];
#pragma unroll
    for (int e = 0; e < NE; e++) p[e] = 0.f;
    const float* row = g_r1 + (size_t)gw * DIMD;
    for (int k = lane; k < DIMD; k += 32) {
        float v = siluf(row[k]);
#pragma unroll
        for (int e = 0; e < NE; e++) p[e] += v * rw2[k * NE + e];
    }
#pragma unroll
    for (int e = 0; e < NE; e++)
        for (int o = 16; o; o >>= 1) p[e] += __shfl_down_sync(0xffffffffu, p[e], o);
    if (lane == 0) {
        float rv[NE];
#pragma unroll
        for (int e = 0; e < NE; e++) rv[e] = p[e] + rb2[e];
        int i1 = 0;
#pragma unroll
        for (int e = 1; e < NE; e++) if (rv[e] > rv[i1]) i1 = e;
        int i2 = (i1 == 0) ? 1 : 0;
#pragma unroll
        for (int e = 0; e < NE; e++) if (e != i1 && rv[e] > rv[i2]) i2 = e;
        float e2 = __expf(rv[i2] - rv[i1]);
        float inv = 1.f / (1.f + e2);
        float w1 = inv, w2 = e2 * inv;
        int p1 = atomicAdd(&g_cnt[i1], 1);
        g_list[i1 * NTOK + p1] = gw;
        g_slot[gw * 2] = i1 * NTOK + p1;
        g_wtok[gw * 2] = w1;
        int p2 = atomicAdd(&g_cnt[i2], 1);
        g_list[i2 * NTOK + p2] = gw;
        g_slot[gw * 2 + 1] = i2 * NTOK + p2;
        g_wtok[gw * 2 + 1] = w2;
    }
}

__global__ void k_combine() {
    int i = blockIdx.x * blockDim.x + threadIdx.x;
    if (i >= NTOK * DIMD) return;
    int n = i / DIMD, d = i % DIMD;
    float v = g_h[i];
    v += g_wtok[n * 2]     * g_eo[(size_t)g_slot[n * 2] * DIMD + d];
    v += g_wtok[n * 2 + 1] * g_eo[(size_t)g_slot[n * 2 + 1] * DIMD + d];
    g_y[i] = v;
}

// pooling partials: grid (BT,16) x 384 threads, deterministic
__global__ void k_pool(const float* __restrict__ sres) {
    int b = blockIdx.x, chunk = blockIdx.y;
    int d = threadIdx.x;
    float sr = sres[d];
    float acc = 0.f;
    int t0 = chunk * (TT / 16);
#pragma unroll 4
    for (int t = t0; t < t0 + TT / 16; t++) {
        size_t i = (size_t)(b * TT + t) * DIMD + d;
        acc += g_x[i] * sr + g_y[i];
    }
    g_pool_part[(b * 16 + chunk) * DIMD + d] = acc;
}

__global__ void k_gate(const float* __restrict__ sw1, const float* __restrict__ sb1,
                       const float* __restrict__ sw2, const float* __restrict__ sb2) {
    int b = blockIdx.x;
    int d = threadIdx.x;  // 384
    __shared__ float pooled[DIMD];
    __shared__ float s1[SQ];
    float acc = 0.f;
#pragma unroll
    for (int c = 0; c < 16; c++) acc += g_pool_part[(b * 16 + c) * DIMD + d];
    pooled[d] = acc / TT;
    __syncthreads();
    if (d < SQ) {
        float a = sb1[d];
        for (int k = 0; k < DIMD; k++) a += pooled[k] * sw1[k * SQ + d];
        s1[d] = siluf(a);
    }
    __syncthreads();
    float ga = sb2[d];
#pragma unroll
    for (int q = 0; q < SQ; q++) ga += s1[q] * sw2[q * DIMD + d];
    g_gate[b * DIMD + d] = 1.f / (1.f + __expf(-ga));
}

__global__ void k_final(const float* __restrict__ res, float* __restrict__ out) {
    int i = blockIdx.x * blockDim.x + threadIdx.x;
    if (i >= NTOK * DIMD) return;
    int b = i / (TT * DIMD);
    int d = i % DIMD;
    out[i] = res[i] + g_y[i] * g_gate[b * DIMD + d];
}

// ---------------- GEMM ----------------
// MODE 0: router1   A=g_hbf         B=g_rw1          C=g_r1(f32)          K=384  N=384
// MODE 1: expert1   A=g_hbf(gather) B=g_we1(perm)    C=g_act1(bf,swiglu)  K=384  N=3072
// MODE 2: expert2   A=g_act1        B=g_we2(perm)    C=g_act2(bf,swiglu)  K=1536 N=3072
// MODE 3: expert3   A=g_act2        B=g_we3          C=g_eo(f32)          K=1536 N=384
#define ALD 40   // As ldm (bf16)
#define BLD 136  // Bs ldm (bf16)
#define CLD 132  // Cs ldm (f32)
#define SSTAGE 3
#define ASZ (128 * ALD * 2)
#define BSZ (32 * BLD * 2)
#define STAGEB (ASZ + BSZ)
#define SMEMSZ (SSTAGE * STAGEB)

template <int MODE>
__global__ void __launch_bounds__(256) k_gemm(const float* __restrict__ bias) {
    constexpr int K  = (MODE <= 1) ? DIMD : INNER;
    constexpr int NC = (MODE == 0 || MODE == 3) ? DIMD : H2;
    constexpr bool GATHER = (MODE == 1);
    constexpr bool USECNT = (MODE != 0);
    constexpr bool FUSE   = (MODE == 1 || MODE == 2);
    constexpr int KT = K / 32;

    int e = blockIdx.z;
    int M = USECNT ? g_cnt[e] : NTOK;
    int m0 = blockIdx.y << 7;
    if (m0 >= M) return;
    int n0 = blockIdx.x << 7;

    extern __shared__ __align__(16) unsigned char smem[];
    float* Cs = (float*)smem;

    int tid = threadIdx.x;

    // A source
    const bf16* Abase;
    if (MODE == 0 || MODE == 1) Abase = g_hbf;
    else if (MODE == 2) Abase = g_act1 + (size_t)e * NTOK * INNER;
    else Abase = g_act2 + (size_t)e * NTOK * INNER;

    int ar0 = tid >> 2;           // rows 0..63
    int acol = (tid & 3) << 3;    // 0,8,16,24
    int gr0 = m0 + ar0, gr1 = m0 + ar0 + 64;
    int sr0 = GATHER ? g_list[e * NTOK + gr0] : gr0;
    int sr1 = GATHER ? g_list[e * NTOK + gr1] : gr1;
    const bf16* aptr0 = Abase + (size_t)sr0 * K + acol;
    const bf16* aptr1 = Abase + (size_t)sr1 * K + acol;

    // B source
    const bf16* Bbase;
    if (MODE == 0) Bbase = g_rw1;
    else if (MODE == 1) Bbase = g_we1 + (size_t)e * DIMD * H2;
    else if (MODE == 2) Bbase = g_we2 + (size_t)e * INNER * H2;
    else Bbase = g_we3 + (size_t)e * INNER * DIMD;

    int br0 = tid >> 4;           // 0..15
    int bcol = (tid & 15) << 3;   // 0..120
    const bf16* bptr0 = Bbase + (size_t)br0 * NC + n0 + bcol;
    const bf16* bptr1 = Bbase + (size_t)(br0 + 16) * NC + n0 + bcol;

    int warpId = tid >> 5, wm = warpId >> 1, wn = warpId & 1;

    wmma::fragment<wmma::accumulator, 16, 16, 16, float> acc[2][4];
#pragma unroll
    for (int i = 0; i < 2; i++)
#pragma unroll
        for (int j = 0; j < 4; j++) wmma::fill_fragment(acc[i][j], 0.f);

    // prologue: load stages 0..S-2
#pragma unroll
    for (int s = 0; s < SSTAGE - 1; s++) {
        bf16* Ad = (bf16*)(smem + s * STAGEB);
        bf16* Bd = (bf16*)(smem + s * STAGEB + ASZ);
        int k0 = s * 32;
        cpa16(Ad + ar0 * ALD + acol, aptr0 + k0);
        cpa16(Ad + (ar0 + 64) * ALD + acol, aptr1 + k0);
        cpa16(Bd + br0 * BLD + bcol, bptr0 + (size_t)k0 * NC);
        cpa16(Bd + (br0 + 16) * BLD + bcol, bptr1 + (size_t)k0 * NC);
        CP_COMMIT;
    }

#pragma unroll 1
    for (int kt = 0; kt < KT; kt++) {
        if (kt == KT - 1) { CP_WAIT0; } else { CP_WAIT1; }
        __syncthreads();
        int pf = kt + SSTAGE - 1;
        if (pf < KT) {
            int sb = pf % SSTAGE;
            bf16* Ad = (bf16*)(smem + sb * STAGEB);
            bf16* Bd = (bf16*)(smem + sb * STAGEB + ASZ);
            int k0 = pf * 32;
            cpa16(Ad + ar0 * ALD + acol, aptr0 + k0);
            cpa16(Ad + (ar0 + 64) * ALD + acol, aptr1 + k0);
            cpa16(Bd + br0 * BLD + bcol, bptr0 + (size_t)k0 * NC);
            cpa16(Bd + (br0 + 16) * BLD + bcol, bptr1 + (size_t)k0 * NC);
            CP_COMMIT;
        }
        int cb = kt % SSTAGE;
        const bf16* Ab = (const bf16*)(smem + cb * STAGEB);
        const bf16* Bb = (const bf16*)(smem + cb * STAGEB + ASZ);
#pragma unroll
        for (int kk = 0; kk < 32; kk += 16) {
            wmma::fragment<wmma::matrix_a, 16, 16, 16, bf16, wmma::row_major> af[2];
            wmma::fragment<wmma::matrix_b, 16, 16, 16, bf16, wmma::row_major> bfm[4];
#pragma unroll
            for (int i = 0; i < 2; i++)
                wmma::load_matrix_sync(af[i], Ab + (wm * 32 + i * 16) * ALD + kk, ALD);
#pragma unroll
            for (int j = 0; j < 4; j++)
                wmma::load_matrix_sync(bfm[j], Bb + kk * BLD + wn * 64 + j * 16, BLD);
#pragma unroll
            for (int i = 0; i < 2; i++)
#pragma unroll
                for (int j = 0; j < 4; j++)
                    wmma::mma_sync(acc[i][j], af[i], bfm[j], acc[i][j]);
        }
    }
    __syncthreads();

    // epilogue in two 64-row halves via shared staging
#pragma unroll
    for (int half = 0; half < 2; half++) {
        if ((wm >> 1) == half) {
#pragma unroll
            for (int i = 0; i < 2; i++)
#pragma unroll
                for (int j = 0; j < 4; j++)
                    wmma::store_matrix_sync(
                        Cs + ((wm & 1) * 32 + i * 16) * CLD + wn * 64 + j * 16,
                        acc[i][j], CLD, wmma::mem_row_major);
        }
        __syncthreads();
        if (FUSE) {
            bf16* dst = ((MODE == 1) ? g_act1 : g_act2) + (size_t)e * NTOK * INNER;
            const float* ba = bias + (size_t)e * H2 + (n0 >> 1);
#pragma unroll
            for (int it = 0; it < 16; it++) {
                int lin = tid + it * 256;       // 4096 pairs
                int r = lin >> 6, p = lin & 63;
                int grow = m0 + half * 64 + r;
                if (grow < M) {
                    float a = Cs[r * CLD + 2 * p]     + ba[p];
                    float g = Cs[r * CLD + 2 * p + 1] + ba[INNER + p];
                    dst[(size_t)grow * INNER + (n0 >> 1) + p] = __float2bfloat16(a * siluf(g));
                }
            }
        } else {
            constexpr int biasStride = (MODE == 0) ? 0 : DIMD;
            size_t cBase = (MODE == 0) ? 0 : (size_t)e * NTOK * DIMD;
            float* dst = (MODE == 0) ? g_r1 : g_eo;
#pragma unroll
            for (int it = 0; it < 32; it++) {
                int lin = tid + it * 256;
                int r = lin >> 7, c = lin & 127;
                int grow = m0 + half * 64 + r;
                if (grow < M) {
                    float v = Cs[r * CLD + c] + bias[(size_t)e * biasStride + n0 + c];
                    dst[cBase + (size_t)grow * NC + n0 + c] = v;
                }
            }
        }
        __syncthreads();
    }
}

// ---------------- launch ----------------
extern "C" void kernel_launch(void* const* d_in, const int* in_sizes, int n_in,
                              void* d_out, int out_size) {
    const float* res    = (const float*)d_in[0];
    const float* ln_g   = (const float*)d_in[1];
    const float* ln_b   = (const float*)d_in[2];
    const float* conv_w = (const float*)d_in[3];
    const float* conv_b = (const float*)d_in[4];
    const float* rw1    = (const float*)d_in[5];
    const float* rb1    = (const float*)d_in[6];
    const float* rw2    = (const float*)d_in[7];
    const float* rb2    = (const float*)d_in[8];
    const float* we1    = (const float*)d_in[9];
    const float* be1    = (const float*)d_in[10];
    const float* we2    = (const float*)d_in[11];
    const float* be2    = (const float*)d_in[12];
    const float* we3    = (const float*)d_in[13];
    const float* be3    = (const float*)d_in[14];
    const float* sw1    = (const float*)d_in[15];
    const float* sb1    = (const float*)d_in[16];
    const float* sw2    = (const float*)d_in[17];
    const float* sb2    = (const float*)d_in[18];
    const float* sres   = (const float*)d_in[19];
    float* out = (float*)d_out;

    static bool attrDone = false;
    if (!attrDone) {
        cudaFuncSetAttribute(k_gemm<0>, cudaFuncAttributeMaxDynamicSharedMemorySize, SMEMSZ);
        cudaFuncSetAttribute(k_gemm<1>, cudaFuncAttributeMaxDynamicSharedMemorySize, SMEMSZ);
        cudaFuncSetAttribute(k_gemm<2>, cudaFuncAttributeMaxDynamicSharedMemorySize, SMEMSZ);
        cudaFuncSetAttribute(k_gemm<3>, cudaFuncAttributeMaxDynamicSharedMemorySize, SMEMSZ);
        attrDone = true;
    }

    // weight conversions (fp32 -> bf16, we1/we2 column-pair permuted)
    k_convert<<<(NE * DIMD * H2 + 255) / 256, 256>>>(we1, 0, NE * DIMD * H2);
    k_convert<<<(NE * INNER * H2 + 255) / 256, 256>>>(we2, 1, NE * INNER * H2);
    k_convert<<<(NE * INNER * DIMD + 255) / 256, 256>>>(we3, 2, NE * INNER * DIMD);
    k_convert<<<(DIMD * DIMD + 255) / 256, 256>>>(rw1, 3, DIMD * DIMD);

    k_ln<<<NTOK, 128>>>(res, ln_g, ln_b);
    k_conv<<<(NTOK * DIMD + 255) / 256, 256>>>(conv_w, conv_b);
    k_zero<<<1, 32>>>();

    k_gemm<0><<<dim3(DIMD / 128, NTOK / 128, 1), 256, SMEMSZ>>>(rb1);
    k_router<<<NTOK / 4, 128>>>(rw2, rb2);

    k_gemm<1><<<dim3(H2 / 128, NTOK / 128, NE), 256, SMEMSZ>>>(be1);  // fc1+swiglu
    k_gemm<2><<<dim3(H2 / 128, NTOK / 128, NE), 256, SMEMSZ>>>(be2);  // fc2+swiglu
    k_gemm<3><<<dim3(DIMD / 128, NTOK / 128, NE), 256, SMEMSZ>>>(be3);

    k_combine<<<(NTOK * DIMD + 255) / 256, 256>>>();
    k_pool<<<dim3(BT, 16), DIMD>>>(sres);
    k_gate<<<BT, DIMD>>>(sw1, sb1, sw2, sb2);
    k_final<<<(NTOK * DIMD + 255) / 256, 256>>>(res, out);
}